// round 1
// baseline (speedup 1.0000x reference)
#include <cuda_runtime.h>
#include <cstdint>
#include <cstddef>

#define DIM      128
#define ROWS     64          // rows per block
#define THREADS  256
#define RPW      8           // rows per warp
#define XPITCH   68          // padded pitch (floats) of transposed x tile
#define KSEL     32

#define SMEM_BYTES (DIM*DIM*4 + DIM*XPITCH*4 + 8*KSEL*8)

__device__ float g_inv_len;

// ---------------------------------------------------------------------------
// helpers
// ---------------------------------------------------------------------------
__device__ __forceinline__ unsigned long long dup_f32(float a) {
    unsigned long long r; unsigned u = __float_as_uint(a);
    asm("mov.b64 %0, {%1, %1};" : "=l"(r) : "r"(u));
    return r;
}
__device__ __forceinline__ void fma2(unsigned long long& c,
                                     unsigned long long a,
                                     unsigned long long b) {
    asm("fma.rn.f32x2 %0, %1, %2, %0;" : "+l"(c) : "l"(a), "l"(b));
}
// order-preserving float -> u32 key (larger float => larger key)
__device__ __forceinline__ unsigned fkey(float f) {
    unsigned u = __float_as_uint(f);
    return (u & 0x80000000u) ? ~u : (u | 0x80000000u);
}

union F2U { unsigned long long u; float2 f; };

// ---------------------------------------------------------------------------
// 1/||v||_F  (one block)
// ---------------------------------------------------------------------------
__global__ void norm_kernel(const float* __restrict__ v) {
    __shared__ float red[8];
    float s = 0.f;
    for (int i = threadIdx.x; i < DIM * DIM; i += blockDim.x) {
        float a = v[i];
        s = fmaf(a, a, s);
    }
    #pragma unroll
    for (int o = 16; o; o >>= 1) s += __shfl_xor_sync(0xffffffffu, s, o);
    if ((threadIdx.x & 31) == 0) red[threadIdx.x >> 5] = s;
    __syncthreads();
    if (threadIdx.x == 0) {
        float t = 0.f;
        #pragma unroll
        for (int i = 0; i < 8; i++) t += red[i];
        g_inv_len = 1.0f / sqrtf(t);
    }
}

// ---------------------------------------------------------------------------
// fused  y = x@v ; top-32 per row ; out = x[idx] * sigmoid(y[idx]/||v||)
// ---------------------------------------------------------------------------
__global__ __launch_bounds__(THREADS, 2)
void pool_kernel(const float* __restrict__ x, const float* __restrict__ v,
                 float* __restrict__ out, int nrows) {
    extern __shared__ float smem[];
    float* v_sh = smem;                          // [128][128] row d contiguous
    float* x_sh = smem + DIM * DIM;              // transposed: [d][row], pitch 68
    uint2* stage = (uint2*)(smem + DIM * DIM + DIM * XPITCH); // [8 warps][32]

    const int tid  = threadIdx.x;
    const int row0 = blockIdx.x * ROWS;

    // ---- load v into SMEM (coalesced float4) ----
    {
        const float4* vg = (const float4*)v;
        float4*       vs = (float4*)v_sh;
        #pragma unroll
        for (int i = tid; i < DIM * DIM / 4; i += THREADS) vs[i] = vg[i];
    }
    // ---- load x tile transposed (coalesced LDG, ~4-way STS conflicts, one-off) ----
    for (int e = tid; e < ROWS * DIM; e += THREADS) {
        int r = e >> 7, d = e & 127;
        float val = (row0 + r < nrows) ? x[(size_t)(row0 + r) * DIM + d] : 0.f;
        x_sh[d * XPITCH + r] = val;
    }
    __syncthreads();

    const int warp = tid >> 5, lane = tid & 31;
    const int r0 = warp * RPW;

    // acc[rowpair][col c]: packed f32x2 holds (row 2p, row 2p+1) for col 4*lane+c
    unsigned long long acc[4][4];
    #pragma unroll
    for (int a = 0; a < 4; a++)
        #pragma unroll
        for (int b = 0; b < 4; b++) acc[a][b] = 0ull;

    const float* vcol = v_sh + lane * 4;
    const float* xrow = x_sh + r0;

    #pragma unroll 4
    for (int d = 0; d < DIM; ++d) {
        float4 vv = *(const float4*)(vcol + (size_t)d * DIM);
        const float* xr = xrow + d * XPITCH;
        unsigned long long x01 = *(const unsigned long long*)(xr + 0);
        unsigned long long x23 = *(const unsigned long long*)(xr + 2);
        unsigned long long x45 = *(const unsigned long long*)(xr + 4);
        unsigned long long x67 = *(const unsigned long long*)(xr + 6);
        unsigned long long v0 = dup_f32(vv.x), v1 = dup_f32(vv.y);
        unsigned long long v2 = dup_f32(vv.z), v3 = dup_f32(vv.w);
        fma2(acc[0][0], x01, v0); fma2(acc[0][1], x01, v1);
        fma2(acc[0][2], x01, v2); fma2(acc[0][3], x01, v3);
        fma2(acc[1][0], x23, v0); fma2(acc[1][1], x23, v1);
        fma2(acc[1][2], x23, v2); fma2(acc[1][3], x23, v3);
        fma2(acc[2][0], x45, v0); fma2(acc[2][1], x45, v1);
        fma2(acc[2][2], x45, v2); fma2(acc[2][3], x45, v3);
        fma2(acc[3][0], x67, v0); fma2(acc[3][1], x67, v1);
        fma2(acc[3][2], x67, v2); fma2(acc[3][3], x67, v3);
    }

    const float inv_len = g_inv_len;
    uint2* st = stage + warp * KSEL;

    // ---- per-row top-32 extraction (sorted desc, jax tie-break: lowest col) ----
    #pragma unroll
    for (int r = 0; r < RPW; ++r) {
        const int grow = row0 + r0 + r;
        if (grow >= nrows) break;   // warp-uniform

        F2U t0, t1, t2, t3;
        t0.u = acc[r >> 1][0]; t1.u = acc[r >> 1][1];
        t2.u = acc[r >> 1][2]; t3.u = acc[r >> 1][3];
        float y0 = (r & 1) ? t0.f.y : t0.f.x;
        float y1 = (r & 1) ? t1.f.y : t1.f.x;
        float y2 = (r & 1) ? t2.f.y : t2.f.x;
        float y3 = (r & 1) ? t3.f.y : t3.f.x;

        unsigned kk0 = fkey(y0), kk1 = fkey(y1), kk2 = fkey(y2), kk3 = fkey(y3);

        #pragma unroll 1
        for (int i = 0; i < KSEL; ++i) {
            unsigned loc = max(max(kk0, kk1), max(kk2, kk3));
            unsigned m   = __reduce_max_sync(0xffffffffu, loc);
            unsigned bal = __ballot_sync(0xffffffffu, loc == m);
            if (lane == __ffs(bal) - 1) {
                int c;
                if      (kk0 == m) { c = 0; kk0 = 0u; }
                else if (kk1 == m) { c = 1; kk1 = 0u; }
                else if (kk2 == m) { c = 2; kk2 = 0u; }
                else               { c = 3; kk3 = 0u; }
                unsigned u = (m & 0x80000000u) ? (m & 0x7fffffffu) : ~m;
                st[i] = make_uint2((unsigned)(lane * 4 + c), u);
            }
        }
        __syncwarp();
        {
            uint2 p   = st[lane];
            float dot = __uint_as_float(p.y);
            float sg  = 1.0f / (1.0f + __expf(-dot * inv_len));
            float xv  = x_sh[p.x * XPITCH + (r0 + r)];
            out[(size_t)grow * KSEL + lane] = xv * sg;
        }
        __syncwarp();
    }
}

// ---------------------------------------------------------------------------
extern "C" void kernel_launch(void* const* d_in, const int* in_sizes, int n_in,
                              void* d_out, int out_size) {
    const float* x = (const float*)d_in[0];
    const float* v = (const float*)d_in[1];
    float* out = (float*)d_out;
    const int nrows = in_sizes[0] / DIM;

    cudaFuncSetAttribute(pool_kernel,
                         cudaFuncAttributeMaxDynamicSharedMemorySize, SMEM_BYTES);

    norm_kernel<<<1, 256>>>(v);
    const int grid = (nrows + ROWS - 1) / ROWS;
    pool_kernel<<<grid, THREADS, SMEM_BYTES>>>(x, v, out, nrows);
}

// round 3
// speedup vs baseline: 1.9237x; 1.9237x over previous
#include <cuda_runtime.h>
#include <cstdint>
#include <cstddef>

#define DIM      128
#define ROWS     64          // rows per block
#define THREADS  256
#define RPW      8           // rows per warp
#define XPITCH   68          // padded pitch (floats) of transposed x tile
#define KSEL     32
#define DHALF    64          // d-rows of v staged per pass

// smem: v half [64][128] + x^T [128][68] + stage [8 warps][2 rows][32] uint2
#define SMEM_BYTES (DHALF*DIM*4 + DIM*XPITCH*4 + 8*2*KSEL*8)

__device__ float g_inv_len;

// ---------------------------------------------------------------------------
// helpers
// ---------------------------------------------------------------------------
__device__ __forceinline__ unsigned long long dup_f32(float a) {
    unsigned long long r; unsigned u = __float_as_uint(a);
    asm("mov.b64 %0, {%1, %1};" : "=l"(r) : "r"(u));
    return r;
}
__device__ __forceinline__ void fma2(unsigned long long& c,
                                     unsigned long long a,
                                     unsigned long long b) {
    asm("fma.rn.f32x2 %0, %1, %2, %0;" : "+l"(c) : "l"(a), "l"(b));
}
// order-preserving float -> u32 key (larger float => larger key)
__device__ __forceinline__ unsigned fkey(float f) {
    unsigned u = __float_as_uint(f);
    return (u & 0x80000000u) ? ~u : (u | 0x80000000u);
}
__device__ __forceinline__ float unfkey(unsigned m) {
    unsigned u = (m & 0x80000000u) ? (m & 0x7fffffffu) : ~m;
    return __uint_as_float(u);
}

union F2U { unsigned long long u; float2 f; };

// stable desc comparator: larger key first; equal keys -> lower col first
#define CSWAP(ka, ca, kb, cb)                                   \
    {                                                           \
        bool sw = (ka < kb) || (ka == kb && ca > cb);           \
        unsigned tk = sw ? kb : ka;                             \
        unsigned tc = sw ? cb : ca;                             \
        kb = sw ? ka : kb;  cb = sw ? ca : cb;                  \
        ka = tk;            ca = tc;                            \
    }

// ---------------------------------------------------------------------------
// 1/||v||_F  (one block)
// ---------------------------------------------------------------------------
__global__ void norm_kernel(const float* __restrict__ v) {
    __shared__ float red[8];
    float s = 0.f;
    for (int i = threadIdx.x; i < DIM * DIM; i += blockDim.x) {
        float a = v[i];
        s = fmaf(a, a, s);
    }
    #pragma unroll
    for (int o = 16; o; o >>= 1) s += __shfl_xor_sync(0xffffffffu, s, o);
    if ((threadIdx.x & 31) == 0) red[threadIdx.x >> 5] = s;
    __syncthreads();
    if (threadIdx.x == 0) {
        float t = 0.f;
        #pragma unroll
        for (int i = 0; i < 8; i++) t += red[i];
        g_inv_len = 1.0f / sqrtf(t);
    }
}

// ---------------------------------------------------------------------------
// fused  y = x@v ; top-32 per row ; out = x[idx] * sigmoid(y[idx]/||v||)
// ---------------------------------------------------------------------------
__global__ __launch_bounds__(THREADS, 3)
void pool_kernel(const float* __restrict__ x, const float* __restrict__ v,
                 float* __restrict__ out, int nrows) {
    extern __shared__ float smem[];
    float* v_sh = smem;                           // [64][128], per pass
    float* x_sh = smem + DHALF * DIM;             // transposed: [d][row], pitch 68
    uint2* stage = (uint2*)(x_sh + DIM * XPITCH); // [8 warps][2][32]

    const int tid  = threadIdx.x;
    const int row0 = blockIdx.x * ROWS;
    const int warp = tid >> 5, lane = tid & 31;
    const int r0 = warp * RPW;

    // ---- load x tile transposed (one-off) ----
    for (int e = tid; e < ROWS * DIM; e += THREADS) {
        int r = e >> 7, d = e & 127;
        float val = (row0 + r < nrows) ? x[(size_t)(row0 + r) * DIM + d] : 0.f;
        x_sh[d * XPITCH + r] = val;
    }

    // lane l owns columns (31-l)*4 .. (31-l)*4+3  (so FLO(ballot) = lowest col)
    const int col0 = (31 - lane) * 4;

    unsigned long long acc[4][4];
    #pragma unroll
    for (int a = 0; a < 4; a++)
        #pragma unroll
        for (int b = 0; b < 4; b++) acc[a][b] = 0ull;

    // ---- GEMM in two d-passes (v staged 64 rows at a time) ----
    #pragma unroll 1
    for (int pass = 0; pass < 2; ++pass) {
        __syncthreads();   // pass0: pairs with x load; pass1: v_sh reuse fence
        {
            const float4* vg = (const float4*)(v + pass * DHALF * DIM);
            float4*       vs = (float4*)v_sh;
            for (int i = tid; i < DHALF * DIM / 4; i += THREADS) vs[i] = vg[i];
        }
        __syncthreads();

        const float* vcol  = v_sh + col0;
        const float* xbase = x_sh + pass * DHALF * XPITCH + r0;

        #pragma unroll 8
        for (int dd = 0; dd < DHALF; ++dd) {
            float4 vv = *(const float4*)(vcol + (size_t)dd * DIM);
            const float* xr = xbase + dd * XPITCH;
            unsigned long long x01 = *(const unsigned long long*)(xr + 0);
            unsigned long long x23 = *(const unsigned long long*)(xr + 2);
            unsigned long long x45 = *(const unsigned long long*)(xr + 4);
            unsigned long long x67 = *(const unsigned long long*)(xr + 6);
            unsigned long long v0 = dup_f32(vv.x), v1 = dup_f32(vv.y);
            unsigned long long v2 = dup_f32(vv.z), v3 = dup_f32(vv.w);
            fma2(acc[0][0], x01, v0); fma2(acc[0][1], x01, v1);
            fma2(acc[0][2], x01, v2); fma2(acc[0][3], x01, v3);
            fma2(acc[1][0], x23, v0); fma2(acc[1][1], x23, v1);
            fma2(acc[1][2], x23, v2); fma2(acc[1][3], x23, v3);
            fma2(acc[2][0], x45, v0); fma2(acc[2][1], x45, v1);
            fma2(acc[2][2], x45, v2); fma2(acc[2][3], x45, v3);
            fma2(acc[3][0], x67, v0); fma2(acc[3][1], x67, v1);
            fma2(acc[3][2], x67, v2); fma2(acc[3][3], x67, v3);
        }
    }

    const float inv_len = g_inv_len;
    uint2* stA = stage + warp * 2 * KSEL;
    uint2* stB = stA + KSEL;

    // ---- top-32 per row: branch-free, two rows interleaved per loop ----
    #pragma unroll
    for (int pr = 0; pr < 4; ++pr) {
        F2U t0, t1, t2, t3;
        t0.u = acc[pr][0]; t1.u = acc[pr][1];
        t2.u = acc[pr][2]; t3.u = acc[pr][3];

        // row A = local row r0+2*pr (low halves), row B = r0+2*pr+1 (high)
        unsigned kA0 = fkey(t0.f.x), kA1 = fkey(t1.f.x),
                 kA2 = fkey(t2.f.x), kA3 = fkey(t3.f.x);
        unsigned kB0 = fkey(t0.f.y), kB1 = fkey(t1.f.y),
                 kB2 = fkey(t2.f.y), kB3 = fkey(t3.f.y);
        unsigned cA0 = col0 + 0, cA1 = col0 + 1, cA2 = col0 + 2, cA3 = col0 + 3;
        unsigned cB0 = cA0, cB1 = cA1, cB2 = cA2, cB3 = cA3;

        // sort each lane's 4 candidates descending (stable on col)
        CSWAP(kA0, cA0, kA1, cA1); CSWAP(kA2, cA2, kA3, cA3);
        CSWAP(kA0, cA0, kA2, cA2); CSWAP(kA1, cA1, kA3, cA3);
        CSWAP(kA1, cA1, kA2, cA2);
        CSWAP(kB0, cB0, kB1, cB1); CSWAP(kB2, cB2, kB3, cB3);
        CSWAP(kB0, cB0, kB2, cB2); CSWAP(kB1, cB1, kB3, cB3);
        CSWAP(kB1, cB1, kB2, cB2);

        #pragma unroll 4
        for (int i = 0; i < KSEL; ++i) {
            unsigned mA = __reduce_max_sync(0xffffffffu, kA0);
            unsigned mB = __reduce_max_sync(0xffffffffu, kB0);
            unsigned balA = __ballot_sync(0xffffffffu, kA0 == mA);
            unsigned balB = __ballot_sync(0xffffffffu, kB0 == mB);
            bool winA = (lane == 31 - __clz(balA));   // FLO -> lowest column
            bool winB = (lane == 31 - __clz(balB));
            if (winA) stA[i] = make_uint2(cA0, kA0);
            if (winB) stB[i] = make_uint2(cB0, kB0);
            kA0 = winA ? kA1 : kA0;  cA0 = winA ? cA1 : cA0;
            kA1 = winA ? kA2 : kA1;  cA1 = winA ? cA2 : cA1;
            kA2 = winA ? kA3 : kA2;  cA2 = winA ? cA3 : cA2;
            kA3 = winA ? 0u  : kA3;
            kB0 = winB ? kB1 : kB0;  cB0 = winB ? cB1 : cB0;
            kB1 = winB ? kB2 : kB1;  cB1 = winB ? cB2 : cB1;
            kB2 = winB ? kB3 : kB2;  cB2 = winB ? cB3 : cB2;
            kB3 = winB ? 0u  : kB3;
        }
        __syncwarp();

        // ---- epilogue: gather x, sigmoid, store (lane i -> rank i) ----
        {
            const int rowA = r0 + 2 * pr;
            const int growA = row0 + rowA;
            uint2 pA = stA[lane];
            uint2 pB = stB[lane];
            float dA = unfkey(pA.y) * inv_len;
            float dB = unfkey(pB.y) * inv_len;
            float sA = 1.0f / (1.0f + __expf(-dA));
            float sB = 1.0f / (1.0f + __expf(-dB));
            float xA = x_sh[pA.x * XPITCH + rowA];
            float xB = x_sh[pB.x * XPITCH + rowA + 1];
            if (growA < nrows)
                out[(size_t)growA * KSEL + lane] = xA * sA;
            if (growA + 1 < nrows)
                out[(size_t)(growA + 1) * KSEL + lane] = xB * sB;
        }
        __syncwarp();
    }
}

// ---------------------------------------------------------------------------
extern "C" void kernel_launch(void* const* d_in, const int* in_sizes, int n_in,
                              void* d_out, int out_size) {
    const float* x = (const float*)d_in[0];
    const float* v = (const float*)d_in[1];
    float* out = (float*)d_out;
    const int nrows = in_sizes[0] / DIM;

    cudaFuncSetAttribute(pool_kernel,
                         cudaFuncAttributeMaxDynamicSharedMemorySize, SMEM_BYTES);

    norm_kernel<<<1, 256>>>(v);
    const int grid = (nrows + ROWS - 1) / ROWS;
    pool_kernel<<<grid, THREADS, SMEM_BYTES>>>(x, v, out, nrows);
}